// round 12
// baseline (speedup 1.0000x reference)
#include <cuda_runtime.h>

#define N_NODES 200000
#define N_EDGES 6400000
#define IN_DIM  1433
#define HID     16
#define OUTD    7
#define OUTP    8
#define SCAN_BLOCKS ((N_NODES + 255) / 256)   // 782
#define KC       16
#define NCHUNK  ((IN_DIM + KC - 1) / KC)       // 90
#define GROWS    256

typedef unsigned long long ull;

// -------- scratch (device globals; no runtime allocation allowed) --------
__device__ float g_XW1[N_NODES * HID];          // 12.8 MB  X @ W1
__device__ float g_H  [N_NODES * HID];          // 12.8 MB  L @ (X W1)
__device__ float g_HW2[N_NODES * OUTP];         //  6.4 MB  relu(H+b1) @ W2, padded to 8
__device__ int   g_cnt   [N_NODES];
__device__ int   g_rowptr[N_NODES + 1];
__device__ int   g_pos   [N_NODES];
__device__ int   g_bsum  [SCAN_BLOCKS];
__device__ int   g_boff  [SCAN_BLOCKS];
__device__ ull   g_edge  [N_EDGES];             // 51.2 MB packed (val, col) sorted by row

// packed fp32x2 helpers (FFMA2: 2 fp32 FMAs / instr, full fp32 precision)
__device__ __forceinline__ ull pack2(float lo, float hi) {
    ull v; asm("mov.b64 %0, {%1, %2};" : "=l"(v) : "f"(lo), "f"(hi)); return v;
}
__device__ __forceinline__ void ffma2(ull& d, ull a, ull b) {
    asm("fma.rn.f32x2 %0, %1, %2, %3;" : "=l"(d) : "l"(a), "l"(b), "l"(d));
}

// -------- zero the row counters --------
__global__ void zero_kernel() {
    int i = blockIdx.x * blockDim.x + threadIdx.x;
    if (i < N_NODES) g_cnt[i] = 0;
}

// -------- count edges per row --------
__global__ void __launch_bounds__(256) count_kernel(const int* __restrict__ erow) {
    int q = blockIdx.x * 256 + threadIdx.x;
    if (q >= N_EDGES / 4) return;
    int4 r4 = ((const int4*)erow)[q];
    asm volatile("red.global.add.u32 [%0], 1;" :: "l"(&g_cnt[r4.x]) : "memory");
    asm volatile("red.global.add.u32 [%0], 1;" :: "l"(&g_cnt[r4.y]) : "memory");
    asm volatile("red.global.add.u32 [%0], 1;" :: "l"(&g_cnt[r4.z]) : "memory");
    asm volatile("red.global.add.u32 [%0], 1;" :: "l"(&g_cnt[r4.w]) : "memory");
}

// -------- exclusive scan of g_cnt -> g_rowptr (3-phase) --------
__global__ void __launch_bounds__(256) scan1_kernel() {
    __shared__ int s[256];
    int t = threadIdx.x;
    int i = blockIdx.x * 256 + t;
    int x = (i < N_NODES) ? g_cnt[i] : 0;
    s[t] = x;
    __syncthreads();
#pragma unroll
    for (int d = 1; d < 256; d <<= 1) {
        int y = (t >= d) ? s[t - d] : 0;
        __syncthreads();
        s[t] += y;
        __syncthreads();
    }
    if (i < N_NODES) g_rowptr[i] = s[t] - x;
    if (t == 255) g_bsum[blockIdx.x] = s[t];
}

// -------- GEMM1  g_XW1 = X @ W1   (200000 x 1433 x 16) --------
// R10 pipeline + DOUBLE-BUFFERED smem: one sync per chunk, prefetch window =
// sync + full compute phase (> DRAM latency), stragglers decoupled from STS.
// 256 threads, 256 rows, 1 row/thread, KC=16. As[2] static smem 34.8KB.
// ~55 regs -> 4 blocks/SM (32 warps), 64KB LDG bytes in flight per SM.
__global__ void __launch_bounds__(256) gemm1_kernel(const float* __restrict__ X,
                                                    const float* __restrict__ W1) {
    __shared__ float As[2][GROWS][KC + 1];            // stride 17: conflict-free cols
    __shared__ __align__(16) float Ws[2][KC][16];

    const int t    = threadIdx.x;
    const int row0 = blockIdx.x * GROWS;
    const int kk   = t & 15;                          // staging k-lane
    const int rb   = t >> 4;                          // staging row base (0..15)
    const bool full_rows = (row0 + GROWS <= N_NODES);

    float v[16];                                      // staged A values
    float wv;                                         // staged W value

    ull acc[8];
#pragma unroll
    for (int j = 0; j < 8; j++) acc[j] = 0ull;

    auto prefA = [&](int c) {
        const int kc = c * KC;
        const float* p = X + (long)(row0 + rb) * IN_DIM + kc + kk;
        if (full_rows && kc + KC <= IN_DIM) {
#pragma unroll
            for (int s = 0; s < 16; s++)
                v[s] = p[(long)(16 * s) * IN_DIM];
        } else {
            const bool kok = (kc + kk < IN_DIM);
#pragma unroll
            for (int s = 0; s < 16; s++) {
                int r = row0 + rb + 16 * s;
                v[s] = (r < N_NODES && kok) ? p[(long)(16 * s) * IN_DIM] : 0.f;
            }
        }
    };
    auto prefW = [&](int c) {
        const int kc = c * KC;
        int k = t >> 4, j = t & 15;                   // 256 threads cover 16x16
        wv = (kc + k < IN_DIM) ? W1[(kc + k) * HID + j] : 0.f;
    };

    prefA(0); prefW(0);

    for (int c = 0; c < NCHUNK; c++) {
        const int buf = c & 1;
        // regs -> smem[buf]  (disjoint from smem[buf^1] possibly still being read)
#pragma unroll
        for (int s = 0; s < 16; s++) As[buf][rb + 16 * s][kk] = v[s];
        Ws[buf][t >> 4][t & 15] = wv;
        // issue next chunk's loads; consumed at next iter's STS (full-iter window)
        if (c + 1 < NCHUNK) { prefA(c + 1); prefW(c + 1); }
        __syncthreads();                              // ONLY sync this iter

        // compute chunk c from smem[buf]
#pragma unroll
        for (int k = 0; k < KC; k++) {
            const ulonglong2* wp = (const ulonglong2*)&Ws[buf][k][0];
            ulonglong2 wa = wp[0], wb = wp[1], wc = wp[2], wd = wp[3];
            float a = As[buf][t][k];
            ull ap = pack2(a, a);
            ffma2(acc[0], ap, wa.x); ffma2(acc[1], ap, wa.y);
            ffma2(acc[2], ap, wb.x); ffma2(acc[3], ap, wb.y);
            ffma2(acc[4], ap, wc.x); ffma2(acc[5], ap, wc.y);
            ffma2(acc[6], ap, wd.x); ffma2(acc[7], ap, wd.y);
        }
        // no trailing sync: next iter writes the other buffer
    }

    int r = row0 + t;
    if (r < N_NODES) {
        ulonglong2* d = (ulonglong2*)&g_XW1[r * HID];
        d[0] = make_ulonglong2(acc[0], acc[1]);
        d[1] = make_ulonglong2(acc[2], acc[3]);
        d[2] = make_ulonglong2(acc[4], acc[5]);
        d[3] = make_ulonglong2(acc[6], acc[7]);
    }
}

__global__ void __launch_bounds__(1024) scan2_kernel() {
    __shared__ int s[1024];
    int t = threadIdx.x;
    int x = (t < SCAN_BLOCKS) ? g_bsum[t] : 0;
    s[t] = x;
    __syncthreads();
#pragma unroll
    for (int d = 1; d < 1024; d <<= 1) {
        int y = (t >= d) ? s[t - d] : 0;
        __syncthreads();
        s[t] += y;
        __syncthreads();
    }
    if (t < SCAN_BLOCKS) g_boff[t] = s[t] - x;
}

__global__ void __launch_bounds__(256) scan3_kernel() {
    int i = blockIdx.x * 256 + threadIdx.x;
    if (i < N_NODES) {
        int v = g_rowptr[i] + g_boff[blockIdx.x];
        g_rowptr[i] = v;
        g_pos[i] = v;
    }
    if (i == 0) g_rowptr[N_NODES] = N_EDGES;
}

// -------- scatter edges into row-sorted packed array --------
__global__ void __launch_bounds__(256) scatter_kernel(const int*   __restrict__ erow,
                                                      const int*   __restrict__ ecol,
                                                      const float* __restrict__ evals) {
    int q = blockIdx.x * 256 + threadIdx.x;
    if (q >= N_EDGES / 4) return;
    int4   r4 = ((const int4*)erow)[q];
    int4   c4 = ((const int4*)ecol)[q];
    float4 v4 = ((const float4*)evals)[q];
    int   rr[4] = {r4.x, r4.y, r4.z, r4.w};
    int   cc[4] = {c4.x, c4.y, c4.z, c4.w};
    float vv[4] = {v4.x, v4.y, v4.z, v4.w};
#pragma unroll
    for (int i = 0; i < 4; i++) {
        int p = atomicAdd(&g_pos[rr[i]], 1);
        g_edge[p] = ((ull)__float_as_uint(vv[i]) << 32) | (unsigned)cc[i];
    }
}

// -------- SPMM1: warp per row, lanes 0-15 even edges / 16-31 odd, 4x unroll --------
__global__ void __launch_bounds__(256) spmm1_kernel() {
    int warp = (blockIdx.x * 256 + threadIdx.x) >> 5;
    if (warp >= N_NODES) return;
    int lane = threadIdx.x & 31;
    int half = lane >> 4;
    int dim  = lane & 15;

    int start = g_rowptr[warp];
    int end   = g_rowptr[warp + 1];

    float acc = 0.f;
    int i = start + half;
    for (; i + 6 < end; i += 8) {
        ull e0 = g_edge[i];
        ull e1 = g_edge[i + 2];
        ull e2 = g_edge[i + 4];
        ull e3 = g_edge[i + 6];
        int c0 = (int)(unsigned)e0;  float v0 = __uint_as_float((unsigned)(e0 >> 32));
        int c1 = (int)(unsigned)e1;  float v1 = __uint_as_float((unsigned)(e1 >> 32));
        int c2 = (int)(unsigned)e2;  float v2 = __uint_as_float((unsigned)(e2 >> 32));
        int c3 = (int)(unsigned)e3;  float v3 = __uint_as_float((unsigned)(e3 >> 32));
        float x0 = g_XW1[c0 * HID + dim];
        float x1 = g_XW1[c1 * HID + dim];
        float x2 = g_XW1[c2 * HID + dim];
        float x3 = g_XW1[c3 * HID + dim];
        acc = fmaf(v0, x0, acc);
        acc = fmaf(v1, x1, acc);
        acc = fmaf(v2, x2, acc);
        acc = fmaf(v3, x3, acc);
    }
    for (; i < end; i += 2) {
        ull e0 = g_edge[i];
        int c0 = (int)(unsigned)e0;  float v0 = __uint_as_float((unsigned)(e0 >> 32));
        acc = fmaf(v0, g_XW1[c0 * HID + dim], acc);
    }
    acc += __shfl_xor_sync(0xffffffff, acc, 16);
    if (half == 0) g_H[warp * HID + dim] = acc;
}

// -------- GEMM2  g_HW2 = relu(g_H + b1) @ W2, padded to 8 cols --------
__global__ void __launch_bounds__(256) gemm2_kernel(const float* __restrict__ b1,
                                                    const float* __restrict__ W2) {
    __shared__ float sW2[HID * OUTD];
    __shared__ float sb1[HID];
    int t = threadIdx.x;
    if (t < HID * OUTD) sW2[t] = W2[t];
    if (t < HID)        sb1[t] = b1[t];
    __syncthreads();

    int i = blockIdx.x * 256 + t;
    if (i >= N_NODES) return;

    const float4* hp = (const float4*)&g_H[i * HID];
    float h[16];
    *(float4*)&h[0]  = hp[0]; *(float4*)&h[4]  = hp[1];
    *(float4*)&h[8]  = hp[2]; *(float4*)&h[12] = hp[3];
#pragma unroll
    for (int j = 0; j < 16; j++) h[j] = fmaxf(h[j] + sb1[j], 0.f);

    float o[OUTP];
#pragma unroll
    for (int c = 0; c < OUTD; c++) {
        float s = 0.f;
#pragma unroll
        for (int j = 0; j < HID; j++) s = fmaf(h[j], sW2[j * OUTD + c], s);
        o[c] = s;
    }
    o[7] = 0.f;

    float4* d = (float4*)&g_HW2[i * OUTP];
    d[0] = *(float4*)&o[0];
    d[1] = *(float4*)&o[4];
}

// -------- SPMM2 + bias fused --------
__global__ void __launch_bounds__(256) spmm2_kernel(const float* __restrict__ b2,
                                                    float* __restrict__ out) {
    int warp = (blockIdx.x * 256 + threadIdx.x) >> 5;
    if (warp >= N_NODES) return;
    int lane = threadIdx.x & 31;
    int sub  = lane >> 3;
    int dim  = lane & 7;

    int start = g_rowptr[warp];
    int end   = g_rowptr[warp + 1];

    float acc = 0.f;
    int i = start + sub;
    for (; i + 12 < end; i += 16) {
        ull e0 = g_edge[i];
        ull e1 = g_edge[i + 4];
        ull e2 = g_edge[i + 8];
        ull e3 = g_edge[i + 12];
        int c0 = (int)(unsigned)e0;  float v0 = __uint_as_float((unsigned)(e0 >> 32));
        int c1 = (int)(unsigned)e1;  float v1 = __uint_as_float((unsigned)(e1 >> 32));
        int c2 = (int)(unsigned)e2;  float v2 = __uint_as_float((unsigned)(e2 >> 32));
        int c3 = (int)(unsigned)e3;  float v3 = __uint_as_float((unsigned)(e3 >> 32));
        float x0 = g_HW2[c0 * OUTP + dim];
        float x1 = g_HW2[c1 * OUTP + dim];
        float x2 = g_HW2[c2 * OUTP + dim];
        float x3 = g_HW2[c3 * OUTP + dim];
        acc = fmaf(v0, x0, acc);
        acc = fmaf(v1, x1, acc);
        acc = fmaf(v2, x2, acc);
        acc = fmaf(v3, x3, acc);
    }
    for (; i < end; i += 4) {
        ull e0 = g_edge[i];
        int c0 = (int)(unsigned)e0;  float v0 = __uint_as_float((unsigned)(e0 >> 32));
        acc = fmaf(v0, g_HW2[c0 * OUTP + dim], acc);
    }
    acc += __shfl_xor_sync(0xffffffff, acc, 8);
    acc += __shfl_xor_sync(0xffffffff, acc, 16);
    if (lane < OUTD) out[warp * OUTD + lane] = acc + b2[lane];
}

extern "C" void kernel_launch(void* const* d_in, const int* in_sizes, int n_in,
                              void* d_out, int out_size) {
    const float* feature = (const float*)d_in[0];
    const int*   erow    = (const int*)  d_in[1];
    const int*   ecol    = (const int*)  d_in[2];
    const float* evals   = (const float*)d_in[3];
    const float* W1      = (const float*)d_in[4];
    const float* b1      = (const float*)d_in[5];
    const float* W2      = (const float*)d_in[6];
    const float* b2      = (const float*)d_in[7];
    float* out = (float*)d_out;

    int quad_blocks  = (N_EDGES / 4 + 255) / 256;          // 6250
    int node_blocks  = (N_NODES + 255) / 256;              // 782
    int warp_blocks  = (N_NODES * 32 + 255) / 256;         // 25000
    int gemm1_blocks = (N_NODES + GROWS - 1) / GROWS;      // 782

    // order keeps gemm1 at launch index 3 -> the kernel ncu captures
    zero_kernel<<<node_blocks, 256>>>();                   // 0
    count_kernel<<<quad_blocks, 256>>>(erow);              // 1
    scan1_kernel<<<SCAN_BLOCKS, 256>>>();                  // 2
    gemm1_kernel<<<gemm1_blocks, 256>>>(feature, W1);      // 3  <- profiled
    scan2_kernel<<<1, 1024>>>();                           // 4
    scan3_kernel<<<SCAN_BLOCKS, 256>>>();                  // 5
    scatter_kernel<<<quad_blocks, 256>>>(erow, ecol, evals);
    spmm1_kernel<<<warp_blocks, 256>>>();
    gemm2_kernel<<<node_blocks, 256>>>(b1, W2);
    spmm2_kernel<<<warp_blocks, 256>>>(b2, out);
}

// round 13
// speedup vs baseline: 1.5306x; 1.5306x over previous
#include <cuda_runtime.h>

#define N_NODES 200000
#define N_EDGES 6400000
#define IN_DIM  1433
#define HID     16
#define OUTD    7
#define OUTP    8
#define SCAN_BLOCKS ((N_NODES + 255) / 256)   // 782
#define KCM      32                            // k-chunk for gemm1
#define MROWS    128                           // rows per gemm1 block (8 warps x 16)
#define NCHM    ((IN_DIM + KCM - 1) / KCM)     // 45

typedef unsigned long long ull;

// -------- scratch (device globals; no runtime allocation allowed) --------
__device__ float g_XW1[N_NODES * HID];          // 12.8 MB  X @ W1
__device__ float g_H  [N_NODES * HID];          // 12.8 MB  L @ (X W1)
__device__ float g_HW2[N_NODES * OUTP];         //  6.4 MB  relu(H+b1) @ W2, padded to 8
__device__ int   g_cnt   [N_NODES];
__device__ int   g_rowptr[N_NODES + 1];
__device__ int   g_pos   [N_NODES];
__device__ int   g_bsum  [SCAN_BLOCKS];
__device__ int   g_boff  [SCAN_BLOCKS];
__device__ ull   g_edge  [N_EDGES];             // 51.2 MB packed (val, col) sorted by row

// tf32 conversion (rna = canonical tf32 rounding; result is a valid fp32 pattern)
__device__ __forceinline__ unsigned f2tf(float x) {
    unsigned r; asm("cvt.rna.tf32.f32 %0, %1;" : "=r"(r) : "f"(x)); return r;
}
// m16n8k8 tf32 MMA, fp32 accumulate
__device__ __forceinline__ void mma_tf32(float& c0, float& c1, float& c2, float& c3,
                                         unsigned a0, unsigned a1, unsigned a2, unsigned a3,
                                         unsigned b0, unsigned b1) {
    asm volatile(
        "mma.sync.aligned.m16n8k8.row.col.f32.tf32.tf32.f32 "
        "{%0,%1,%2,%3}, {%4,%5,%6,%7}, {%8,%9}, {%0,%1,%2,%3};"
        : "+f"(c0), "+f"(c1), "+f"(c2), "+f"(c3)
        : "r"(a0), "r"(a1), "r"(a2), "r"(a3), "r"(b0), "r"(b1));
}

// -------- zero the row counters --------
__global__ void zero_kernel() {
    int i = blockIdx.x * blockDim.x + threadIdx.x;
    if (i < N_NODES) g_cnt[i] = 0;
}

// -------- count edges per row --------
__global__ void __launch_bounds__(256) count_kernel(const int* __restrict__ erow) {
    int q = blockIdx.x * 256 + threadIdx.x;
    if (q >= N_EDGES / 4) return;
    int4 r4 = ((const int4*)erow)[q];
    asm volatile("red.global.add.u32 [%0], 1;" :: "l"(&g_cnt[r4.x]) : "memory");
    asm volatile("red.global.add.u32 [%0], 1;" :: "l"(&g_cnt[r4.y]) : "memory");
    asm volatile("red.global.add.u32 [%0], 1;" :: "l"(&g_cnt[r4.z]) : "memory");
    asm volatile("red.global.add.u32 [%0], 1;" :: "l"(&g_cnt[r4.w]) : "memory");
}

// -------- exclusive scan of g_cnt -> g_rowptr (3-phase) --------
__global__ void __launch_bounds__(256) scan1_kernel() {
    __shared__ int s[256];
    int t = threadIdx.x;
    int i = blockIdx.x * 256 + t;
    int x = (i < N_NODES) ? g_cnt[i] : 0;
    s[t] = x;
    __syncthreads();
#pragma unroll
    for (int d = 1; d < 256; d <<= 1) {
        int y = (t >= d) ? s[t - d] : 0;
        __syncthreads();
        s[t] += y;
        __syncthreads();
    }
    if (i < N_NODES) g_rowptr[i] = s[t] - x;
    if (t == 255) g_bsum[blockIdx.x] = s[t];
}

// -------- GEMM1  g_XW1 = X @ W1   (200000 x 1433 x 16)  — TENSOR CORE --------
// mma.sync.m16n8k8.tf32 with 2-term A-split (a = a_hi + a_lo, both vs W_hi):
// only W1's tf32 rounding survives (~1.5e-4 norm rel err << 1e-3 threshold).
// 8 warps x 16 rows = 128 rows/block; per k8 per warp: 8 conflict-free LDS
// wavefronts feed 16x16x8 MACs (0.06 wf/row-k vs 0.156 scalar best).
// R10 register-prefetch staging pipeline retained.
__global__ void __launch_bounds__(256) gemm1_kernel(const float* __restrict__ X,
                                                    const float* __restrict__ W1) {
    __shared__ float As[MROWS][36];                   // stride 36: frag banks 4g+ti distinct
    __shared__ float Ws[KCM][24];                     // stride 24: frag banks 24ti+g distinct

    const int t    = threadIdx.x;
    const int row0 = blockIdx.x * MROWS;
    const int lane = t & 31;
    const int wid  = t >> 5;
    const int wrow = wid * 16;                        // warp's 16-row tile
    const int gq   = lane >> 2;                       // fragment group 0..7
    const int ti   = lane & 3;                        // fragment thread-in-group
    const bool full_rows = (row0 + MROWS <= N_NODES);

    float v[16];                                      // staged A values
    float wv[2];                                      // staged W values
    float c[2][4];                                    // 2 n-tiles x 4 accum
#pragma unroll
    for (int n = 0; n < 2; n++)
#pragma unroll
        for (int j = 0; j < 4; j++) c[n][j] = 0.f;

    auto prefA = [&](int cc) {
        const int kc = cc * KCM;
        const int r  = t >> 5;                        // rows r + 8s (s=0..15)
        const int k  = t & 31;
        const float* p = X + (long)(row0 + r) * IN_DIM + kc + k;
        if (full_rows && kc + KCM <= IN_DIM) {
#pragma unroll
            for (int s = 0; s < 16; s++) v[s] = p[(long)(8 * s) * IN_DIM];
        } else {
            const bool kok = (kc + k < IN_DIM);
#pragma unroll
            for (int s = 0; s < 16; s++) {
                int rr = row0 + r + 8 * s;
                v[s] = (rr < N_NODES && kok) ? p[(long)(8 * s) * IN_DIM] : 0.f;
            }
        }
    };
    auto prefW = [&](int cc) {
        const int kc = cc * KCM;
#pragma unroll
        for (int s = 0; s < 2; s++) {
            int flat = t + 256 * s;
            int k = flat >> 4, j = flat & 15;
            wv[s] = (kc + k < IN_DIM) ? W1[(kc + k) * HID + j] : 0.f;
        }
    };

    prefA(0); prefW(0);

    for (int cc = 0; cc < NCHM; cc++) {
        // regs -> smem
        {
            const int r = t >> 5, k = t & 31;
#pragma unroll
            for (int s = 0; s < 16; s++) As[r + 8 * s][k] = v[s];
#pragma unroll
            for (int s = 0; s < 2; s++) {
                int flat = t + 256 * s;
                Ws[flat >> 4][flat & 15] = wv[s];
            }
        }
        __syncthreads();

        if (cc + 1 < NCHM) { prefA(cc + 1); prefW(cc + 1); }

        // compute: 4 k8 steps, 2 n-tiles, 2-term split
#pragma unroll
        for (int k8 = 0; k8 < 4; k8++) {
            const int k0 = k8 * 8;
            float a0f = As[wrow + gq    ][k0 + ti    ];
            float a1f = As[wrow + gq + 8][k0 + ti    ];
            float a2f = As[wrow + gq    ][k0 + ti + 4];
            float a3f = As[wrow + gq + 8][k0 + ti + 4];
            unsigned ah0 = f2tf(a0f), ah1 = f2tf(a1f), ah2 = f2tf(a2f), ah3 = f2tf(a3f);
            unsigned al0 = f2tf(a0f - __uint_as_float(ah0));
            unsigned al1 = f2tf(a1f - __uint_as_float(ah1));
            unsigned al2 = f2tf(a2f - __uint_as_float(ah2));
            unsigned al3 = f2tf(a3f - __uint_as_float(ah3));
#pragma unroll
            for (int n = 0; n < 2; n++) {
                unsigned b0 = f2tf(Ws[k0 + ti    ][8 * n + gq]);
                unsigned b1 = f2tf(Ws[k0 + ti + 4][8 * n + gq]);
                mma_tf32(c[n][0], c[n][1], c[n][2], c[n][3], ah0, ah1, ah2, ah3, b0, b1);
                mma_tf32(c[n][0], c[n][1], c[n][2], c[n][3], al0, al1, al2, al3, b0, b1);
            }
        }
        __syncthreads();
    }

    // epilogue: c[n][0,1] -> row wrow+gq, cols 8n+2ti,+1; c[n][2,3] -> row wrow+gq+8
    const int r0 = row0 + wrow + gq;
    const int r1 = r0 + 8;
#pragma unroll
    for (int n = 0; n < 2; n++) {
        const int col = 8 * n + 2 * ti;
        if (r0 < N_NODES) *(float2*)&g_XW1[r0 * HID + col] = make_float2(c[n][0], c[n][1]);
        if (r1 < N_NODES) *(float2*)&g_XW1[r1 * HID + col] = make_float2(c[n][2], c[n][3]);
    }
}

__global__ void __launch_bounds__(1024) scan2_kernel() {
    __shared__ int s[1024];
    int t = threadIdx.x;
    int x = (t < SCAN_BLOCKS) ? g_bsum[t] : 0;
    s[t] = x;
    __syncthreads();
#pragma unroll
    for (int d = 1; d < 1024; d <<= 1) {
        int y = (t >= d) ? s[t - d] : 0;
        __syncthreads();
        s[t] += y;
        __syncthreads();
    }
    if (t < SCAN_BLOCKS) g_boff[t] = s[t] - x;
}

__global__ void __launch_bounds__(256) scan3_kernel() {
    int i = blockIdx.x * 256 + threadIdx.x;
    if (i < N_NODES) {
        int v = g_rowptr[i] + g_boff[blockIdx.x];
        g_rowptr[i] = v;
        g_pos[i] = v;
    }
    if (i == 0) g_rowptr[N_NODES] = N_EDGES;
}

// -------- scatter edges into row-sorted packed array --------
__global__ void __launch_bounds__(256) scatter_kernel(const int*   __restrict__ erow,
                                                      const int*   __restrict__ ecol,
                                                      const float* __restrict__ evals) {
    int q = blockIdx.x * 256 + threadIdx.x;
    if (q >= N_EDGES / 4) return;
    int4   r4 = ((const int4*)erow)[q];
    int4   c4 = ((const int4*)ecol)[q];
    float4 v4 = ((const float4*)evals)[q];
    int   rr[4] = {r4.x, r4.y, r4.z, r4.w};
    int   cc[4] = {c4.x, c4.y, c4.z, c4.w};
    float vv[4] = {v4.x, v4.y, v4.z, v4.w};
#pragma unroll
    for (int i = 0; i < 4; i++) {
        int p = atomicAdd(&g_pos[rr[i]], 1);
        g_edge[p] = ((ull)__float_as_uint(vv[i]) << 32) | (unsigned)cc[i];
    }
}

// -------- SPMM1: warp per row, lanes 0-15 even edges / 16-31 odd, 4x unroll --------
__global__ void __launch_bounds__(256) spmm1_kernel() {
    int warp = (blockIdx.x * 256 + threadIdx.x) >> 5;
    if (warp >= N_NODES) return;
    int lane = threadIdx.x & 31;
    int half = lane >> 4;
    int dim  = lane & 15;

    int start = g_rowptr[warp];
    int end   = g_rowptr[warp + 1];

    float acc = 0.f;
    int i = start + half;
    for (; i + 6 < end; i += 8) {
        ull e0 = g_edge[i];
        ull e1 = g_edge[i + 2];
        ull e2 = g_edge[i + 4];
        ull e3 = g_edge[i + 6];
        int c0 = (int)(unsigned)e0;  float v0 = __uint_as_float((unsigned)(e0 >> 32));
        int c1 = (int)(unsigned)e1;  float v1 = __uint_as_float((unsigned)(e1 >> 32));
        int c2 = (int)(unsigned)e2;  float v2 = __uint_as_float((unsigned)(e2 >> 32));
        int c3 = (int)(unsigned)e3;  float v3 = __uint_as_float((unsigned)(e3 >> 32));
        float x0 = g_XW1[c0 * HID + dim];
        float x1 = g_XW1[c1 * HID + dim];
        float x2 = g_XW1[c2 * HID + dim];
        float x3 = g_XW1[c3 * HID + dim];
        acc = fmaf(v0, x0, acc);
        acc = fmaf(v1, x1, acc);
        acc = fmaf(v2, x2, acc);
        acc = fmaf(v3, x3, acc);
    }
    for (; i < end; i += 2) {
        ull e0 = g_edge[i];
        int c0 = (int)(unsigned)e0;  float v0 = __uint_as_float((unsigned)(e0 >> 32));
        acc = fmaf(v0, g_XW1[c0 * HID + dim], acc);
    }
    acc += __shfl_xor_sync(0xffffffff, acc, 16);
    if (half == 0) g_H[warp * HID + dim] = acc;
}

// -------- GEMM2  g_HW2 = relu(g_H + b1) @ W2, padded to 8 cols --------
__global__ void __launch_bounds__(256) gemm2_kernel(const float* __restrict__ b1,
                                                    const float* __restrict__ W2) {
    __shared__ float sW2[HID * OUTD];
    __shared__ float sb1[HID];
    int t = threadIdx.x;
    if (t < HID * OUTD) sW2[t] = W2[t];
    if (t < HID)        sb1[t] = b1[t];
    __syncthreads();

    int i = blockIdx.x * 256 + t;
    if (i >= N_NODES) return;

    const float4* hp = (const float4*)&g_H[i * HID];
    float h[16];
    *(float4*)&h[0]  = hp[0]; *(float4*)&h[4]  = hp[1];
    *(float4*)&h[8]  = hp[2]; *(float4*)&h[12] = hp[3];
#pragma unroll
    for (int j = 0; j < 16; j++) h[j] = fmaxf(h[j] + sb1[j], 0.f);

    float o[OUTP];
#pragma unroll
    for (int c = 0; c < OUTD; c++) {
        float s = 0.f;
#pragma unroll
        for (int j = 0; j < HID; j++) s = fmaf(h[j], sW2[j * OUTD + c], s);
        o[c] = s;
    }
    o[7] = 0.f;

    float4* d = (float4*)&g_HW2[i * OUTP];
    d[0] = *(float4*)&o[0];
    d[1] = *(float4*)&o[4];
}

// -------- SPMM2 + bias fused --------
__global__ void __launch_bounds__(256) spmm2_kernel(const float* __restrict__ b2,
                                                    float* __restrict__ out) {
    int warp = (blockIdx.x * 256 + threadIdx.x) >> 5;
    if (warp >= N_NODES) return;
    int lane = threadIdx.x & 31;
    int sub  = lane >> 3;
    int dim  = lane & 7;

    int start = g_rowptr[warp];
    int end   = g_rowptr[warp + 1];

    float acc = 0.f;
    int i = start + sub;
    for (; i + 12 < end; i += 16) {
        ull e0 = g_edge[i];
        ull e1 = g_edge[i + 4];
        ull e2 = g_edge[i + 8];
        ull e3 = g_edge[i + 12];
        int c0 = (int)(unsigned)e0;  float v0 = __uint_as_float((unsigned)(e0 >> 32));
        int c1 = (int)(unsigned)e1;  float v1 = __uint_as_float((unsigned)(e1 >> 32));
        int c2 = (int)(unsigned)e2;  float v2 = __uint_as_float((unsigned)(e2 >> 32));
        int c3 = (int)(unsigned)e3;  float v3 = __uint_as_float((unsigned)(e3 >> 32));
        float x0 = g_HW2[c0 * OUTP + dim];
        float x1 = g_HW2[c1 * OUTP + dim];
        float x2 = g_HW2[c2 * OUTP + dim];
        float x3 = g_HW2[c3 * OUTP + dim];
        acc = fmaf(v0, x0, acc);
        acc = fmaf(v1, x1, acc);
        acc = fmaf(v2, x2, acc);
        acc = fmaf(v3, x3, acc);
    }
    for (; i < end; i += 4) {
        ull e0 = g_edge[i];
        int c0 = (int)(unsigned)e0;  float v0 = __uint_as_float((unsigned)(e0 >> 32));
        acc = fmaf(v0, g_HW2[c0 * OUTP + dim], acc);
    }
    acc += __shfl_xor_sync(0xffffffff, acc, 8);
    acc += __shfl_xor_sync(0xffffffff, acc, 16);
    if (lane < OUTD) out[warp * OUTD + lane] = acc + b2[lane];
}

extern "C" void kernel_launch(void* const* d_in, const int* in_sizes, int n_in,
                              void* d_out, int out_size) {
    const float* feature = (const float*)d_in[0];
    const int*   erow    = (const int*)  d_in[1];
    const int*   ecol    = (const int*)  d_in[2];
    const float* evals   = (const float*)d_in[3];
    const float* W1      = (const float*)d_in[4];
    const float* b1      = (const float*)d_in[5];
    const float* W2      = (const float*)d_in[6];
    const float* b2      = (const float*)d_in[7];
    float* out = (float*)d_out;

    int quad_blocks  = (N_EDGES / 4 + 255) / 256;          // 6250
    int node_blocks  = (N_NODES + 255) / 256;              // 782
    int warp_blocks  = (N_NODES * 32 + 255) / 256;         // 25000
    int gemm1_blocks = (N_NODES + MROWS - 1) / MROWS;      // 1563

    // order keeps gemm1 at launch index 3 -> the kernel ncu captures
    zero_kernel<<<node_blocks, 256>>>();                   // 0
    count_kernel<<<quad_blocks, 256>>>(erow);              // 1
    scan1_kernel<<<SCAN_BLOCKS, 256>>>();                  // 2
    gemm1_kernel<<<gemm1_blocks, 256>>>(feature, W1);      // 3  <- profiled
    scan2_kernel<<<1, 1024>>>();                           // 4
    scan3_kernel<<<SCAN_BLOCKS, 256>>>();                  // 5
    scatter_kernel<<<quad_blocks, 256>>>(erow, ecol, evals);
    spmm1_kernel<<<warp_blocks, 256>>>();
    gemm2_kernel<<<node_blocks, 256>>>(b1, W2);
    spmm2_kernel<<<warp_blocks, 256>>>(b2, out);
}

// round 14
// speedup vs baseline: 1.5589x; 1.0185x over previous
#include <cuda_runtime.h>

#define N_NODES 200000
#define N_EDGES 6400000
#define IN_DIM  1433
#define HID     16
#define OUTD    7
#define OUTP    8
#define SCAN_BLOCKS ((N_NODES + 255) / 256)   // 782
#define KCM      32                            // k-chunk for gemm1
#define MROWS    128                           // rows per gemm1 block (8 warps x 16)
#define NCHM    ((IN_DIM + KCM - 1) / KCM)     // 45
#define GEMM_BLOCKS ((N_NODES + MROWS - 1) / MROWS)   // 1563
#define COUNT_BLOCKS ((N_EDGES / 4 + 255) / 256)      // 6250
#define FAT_BLOCKS (GEMM_BLOCKS + COUNT_BLOCKS)       // 7813

typedef unsigned long long ull;

// -------- scratch (device globals; no runtime allocation allowed) --------
__device__ float g_XW1[N_NODES * HID];          // 12.8 MB  X @ W1
__device__ float g_H  [N_NODES * HID];          // 12.8 MB  L @ (X W1)
__device__ float g_HW2[N_NODES * OUTP];         //  6.4 MB  relu(H+b1) @ W2, padded to 8
__device__ int   g_cnt   [N_NODES];
__device__ int   g_rowptr[N_NODES + 1];
__device__ int   g_pos   [N_NODES];
__device__ int   g_bsum  [SCAN_BLOCKS];
__device__ int   g_boff  [SCAN_BLOCKS];
__device__ ull   g_edge  [N_EDGES];             // 51.2 MB packed (val, col) sorted by row

// tf32 conversion (rna = canonical tf32 rounding; result is a valid fp32 pattern)
__device__ __forceinline__ unsigned f2tf(float x) {
    unsigned r; asm("cvt.rna.tf32.f32 %0, %1;" : "=r"(r) : "f"(x)); return r;
}
// m16n8k8 tf32 MMA, fp32 accumulate
__device__ __forceinline__ void mma_tf32(float& c0, float& c1, float& c2, float& c3,
                                         unsigned a0, unsigned a1, unsigned a2, unsigned a3,
                                         unsigned b0, unsigned b1) {
    asm volatile(
        "mma.sync.aligned.m16n8k8.row.col.f32.tf32.tf32.f32 "
        "{%0,%1,%2,%3}, {%4,%5,%6,%7}, {%8,%9}, {%0,%1,%2,%3};"
        : "+f"(c0), "+f"(c1), "+f"(c2), "+f"(c3)
        : "r"(a0), "r"(a1), "r"(a2), "r"(a3), "r"(b0), "r"(b1));
}

// -------- zero the row counters (3 partial launches -> fat kernel at idx 3) --------
__global__ void zero_kernel(int off) {
    int i = off + blockIdx.x * blockDim.x + threadIdx.x;
    if (i < N_NODES) g_cnt[i] = 0;
}

// -------- FAT kernel: gemm1 (tensor core, W-split tf32) || count (atomics) --------
// Blocks with bid%5==0 run gemm1 tiles; others run edge counting concurrently,
// overlapping the atomic/L2 pipe with gemm1's DRAM stream.
__global__ void __launch_bounds__(256) gemm1_count_kernel(const float* __restrict__ X,
                                                          const float* __restrict__ W1,
                                                          const int*   __restrict__ erow) {
    __shared__ float As[MROWS][36];                   // frag banks 4g+ti distinct
    __shared__ unsigned Wh[KCM][24];                  // tf32 hi, banks 24ti+g distinct
    __shared__ unsigned Wl[KCM][24];                  // tf32 lo

    const int bid = blockIdx.x;
    const int g5  = bid / 5;
    if (bid % 5 != 0) {
        // ---------------- count block ----------------
        int cb = bid - g5 - 1;                        // 0..COUNT_BLOCKS-1
        int q  = cb * 256 + threadIdx.x;
        if (q < N_EDGES / 4) {
            int4 r4 = ((const int4*)erow)[q];
            asm volatile("red.global.add.u32 [%0], 1;" :: "l"(&g_cnt[r4.x]) : "memory");
            asm volatile("red.global.add.u32 [%0], 1;" :: "l"(&g_cnt[r4.y]) : "memory");
            asm volatile("red.global.add.u32 [%0], 1;" :: "l"(&g_cnt[r4.z]) : "memory");
            asm volatile("red.global.add.u32 [%0], 1;" :: "l"(&g_cnt[r4.w]) : "memory");
        }
        return;
    }
    // ---------------- gemm1 block ----------------
    const int t    = threadIdx.x;
    const int row0 = g5 * MROWS;
    if (row0 >= N_NODES) return;
    const int lane = t & 31;
    const int wid  = t >> 5;
    const int wrow = wid * 16;
    const int gq   = lane >> 2;
    const int ti   = lane & 3;
    const bool full_rows = (row0 + MROWS <= N_NODES);

    float v[16];                                      // staged A values
    float wv[2];                                      // staged W values
    float c[2][4];
#pragma unroll
    for (int n = 0; n < 2; n++)
#pragma unroll
        for (int j = 0; j < 4; j++) c[n][j] = 0.f;

    auto prefA = [&](int cc) {
        const int kc = cc * KCM;
        const int r  = t >> 5;
        const int k  = t & 31;
        const float* p = X + (long)(row0 + r) * IN_DIM + kc + k;
        if (full_rows && kc + KCM <= IN_DIM) {
#pragma unroll
            for (int s = 0; s < 16; s++) v[s] = p[(long)(8 * s) * IN_DIM];
        } else {
            const bool kok = (kc + k < IN_DIM);
#pragma unroll
            for (int s = 0; s < 16; s++) {
                int rr = row0 + r + 8 * s;
                v[s] = (rr < N_NODES && kok) ? p[(long)(8 * s) * IN_DIM] : 0.f;
            }
        }
    };
    auto prefW = [&](int cc) {
        const int kc = cc * KCM;
#pragma unroll
        for (int s = 0; s < 2; s++) {
            int flat = t + 256 * s;
            int k = flat >> 4, j = flat & 15;
            wv[s] = (kc + k < IN_DIM) ? W1[(kc + k) * HID + j] : 0.f;
        }
    };

    prefA(0); prefW(0);

    for (int cc = 0; cc < NCHM; cc++) {
        // regs -> smem; W split into tf32 hi/lo at staging time (once per chunk)
        {
            const int r = t >> 5, k = t & 31;
#pragma unroll
            for (int s = 0; s < 16; s++) As[r + 8 * s][k] = v[s];
#pragma unroll
            for (int s = 0; s < 2; s++) {
                int flat = t + 256 * s;
                int kk = flat >> 4, jj = flat & 15;
                float w = wv[s];
                unsigned hi = f2tf(w);
                unsigned lo = f2tf(w - __uint_as_float(hi));
                Wh[kk][jj] = hi;
                Wl[kk][jj] = lo;
            }
        }
        __syncthreads();

        if (cc + 1 < NCHM) { prefA(cc + 1); prefW(cc + 1); }

        // compute: 4 k8 steps, 2 n-tiles, 2 MMAs (W_hi, W_lo) per n-tile
#pragma unroll
        for (int k8 = 0; k8 < 4; k8++) {
            const int k0 = k8 * 8;
            unsigned a0 = f2tf(As[wrow + gq    ][k0 + ti    ]);
            unsigned a1 = f2tf(As[wrow + gq + 8][k0 + ti    ]);
            unsigned a2 = f2tf(As[wrow + gq    ][k0 + ti + 4]);
            unsigned a3 = f2tf(As[wrow + gq + 8][k0 + ti + 4]);
#pragma unroll
            for (int n = 0; n < 2; n++) {
                unsigned bh0 = Wh[k0 + ti    ][8 * n + gq];
                unsigned bh1 = Wh[k0 + ti + 4][8 * n + gq];
                unsigned bl0 = Wl[k0 + ti    ][8 * n + gq];
                unsigned bl1 = Wl[k0 + ti + 4][8 * n + gq];
                mma_tf32(c[n][0], c[n][1], c[n][2], c[n][3], a0, a1, a2, a3, bh0, bh1);
                mma_tf32(c[n][0], c[n][1], c[n][2], c[n][3], a0, a1, a2, a3, bl0, bl1);
            }
        }
        __syncthreads();
    }

    const int r0 = row0 + wrow + gq;
    const int r1 = r0 + 8;
#pragma unroll
    for (int n = 0; n < 2; n++) {
        const int col = 8 * n + 2 * ti;
        if (r0 < N_NODES) *(float2*)&g_XW1[r0 * HID + col] = make_float2(c[n][0], c[n][1]);
        if (r1 < N_NODES) *(float2*)&g_XW1[r1 * HID + col] = make_float2(c[n][2], c[n][3]);
    }
}

// -------- exclusive scan of g_cnt -> g_rowptr (3-phase) --------
__global__ void __launch_bounds__(256) scan1_kernel() {
    __shared__ int s[256];
    int t = threadIdx.x;
    int i = blockIdx.x * 256 + t;
    int x = (i < N_NODES) ? g_cnt[i] : 0;
    s[t] = x;
    __syncthreads();
#pragma unroll
    for (int d = 1; d < 256; d <<= 1) {
        int y = (t >= d) ? s[t - d] : 0;
        __syncthreads();
        s[t] += y;
        __syncthreads();
    }
    if (i < N_NODES) g_rowptr[i] = s[t] - x;
    if (t == 255) g_bsum[blockIdx.x] = s[t];
}

__global__ void __launch_bounds__(1024) scan2_kernel() {
    __shared__ int s[1024];
    int t = threadIdx.x;
    int x = (t < SCAN_BLOCKS) ? g_bsum[t] : 0;
    s[t] = x;
    __syncthreads();
#pragma unroll
    for (int d = 1; d < 1024; d <<= 1) {
        int y = (t >= d) ? s[t - d] : 0;
        __syncthreads();
        s[t] += y;
        __syncthreads();
    }
    if (t < SCAN_BLOCKS) g_boff[t] = s[t] - x;
}

__global__ void __launch_bounds__(256) scan3_kernel() {
    int i = blockIdx.x * 256 + threadIdx.x;
    if (i < N_NODES) {
        int v = g_rowptr[i] + g_boff[blockIdx.x];
        g_rowptr[i] = v;
        g_pos[i] = v;
    }
    if (i == 0) g_rowptr[N_NODES] = N_EDGES;
}

// -------- scatter edges into row-sorted packed array --------
__global__ void __launch_bounds__(256) scatter_kernel(const int*   __restrict__ erow,
                                                      const int*   __restrict__ ecol,
                                                      const float* __restrict__ evals) {
    int q = blockIdx.x * 256 + threadIdx.x;
    if (q >= N_EDGES / 4) return;
    int4   r4 = ((const int4*)erow)[q];
    int4   c4 = ((const int4*)ecol)[q];
    float4 v4 = ((const float4*)evals)[q];
    int   rr[4] = {r4.x, r4.y, r4.z, r4.w};
    int   cc[4] = {c4.x, c4.y, c4.z, c4.w};
    float vv[4] = {v4.x, v4.y, v4.z, v4.w};
#pragma unroll
    for (int i = 0; i < 4; i++) {
        int p = atomicAdd(&g_pos[rr[i]], 1);
        g_edge[p] = ((ull)__float_as_uint(vv[i]) << 32) | (unsigned)cc[i];
    }
}

// -------- SPMM1: warp per row, 4 lanes per edge (float4 gathers), 8 edges/iter --------
__global__ void __launch_bounds__(256) spmm1_kernel() {
    int warp = (blockIdx.x * 256 + threadIdx.x) >> 5;
    if (warp >= N_NODES) return;
    int lane = threadIdx.x & 31;
    int e    = lane >> 2;                 // edge sub-slot 0..7
    int dg   = lane & 3;                  // dim group (4 floats)

    int start = g_rowptr[warp];
    int end   = g_rowptr[warp + 1];

    float4 acc = make_float4(0.f, 0.f, 0.f, 0.f);
    int i = start + e;
    for (; i + 8 < end; i += 16) {        // 2 edges per lane-slot in flight
        ull e0 = g_edge[i];
        ull e1 = g_edge[i + 8];
        int   c0 = (int)(unsigned)e0;  float v0 = __uint_as_float((unsigned)(e0 >> 32));
        int   c1 = (int)(unsigned)e1;  float v1 = __uint_as_float((unsigned)(e1 >> 32));
        float4 x0 = *(const float4*)&g_XW1[c0 * HID + 4 * dg];
        float4 x1 = *(const float4*)&g_XW1[c1 * HID + 4 * dg];
        acc.x = fmaf(v0, x0.x, acc.x); acc.y = fmaf(v0, x0.y, acc.y);
        acc.z = fmaf(v0, x0.z, acc.z); acc.w = fmaf(v0, x0.w, acc.w);
        acc.x = fmaf(v1, x1.x, acc.x); acc.y = fmaf(v1, x1.y, acc.y);
        acc.z = fmaf(v1, x1.z, acc.z); acc.w = fmaf(v1, x1.w, acc.w);
    }
    if (i < end) {
        ull e0 = g_edge[i];
        int   c0 = (int)(unsigned)e0;  float v0 = __uint_as_float((unsigned)(e0 >> 32));
        float4 x0 = *(const float4*)&g_XW1[c0 * HID + 4 * dg];
        acc.x = fmaf(v0, x0.x, acc.x); acc.y = fmaf(v0, x0.y, acc.y);
        acc.z = fmaf(v0, x0.z, acc.z); acc.w = fmaf(v0, x0.w, acc.w);
    }
    // reduce across edge sub-slots (lane bits 2,3,4)
#pragma unroll
    for (int m = 4; m <= 16; m <<= 1) {
        acc.x += __shfl_xor_sync(0xffffffff, acc.x, m);
        acc.y += __shfl_xor_sync(0xffffffff, acc.y, m);
        acc.z += __shfl_xor_sync(0xffffffff, acc.z, m);
        acc.w += __shfl_xor_sync(0xffffffff, acc.w, m);
    }
    if (lane < 4) *(float4*)&g_H[warp * HID + 4 * lane] = acc;
}

// -------- GEMM2  g_HW2 = relu(g_H + b1) @ W2, padded to 8 cols --------
__global__ void __launch_bounds__(256) gemm2_kernel(const float* __restrict__ b1,
                                                    const float* __restrict__ W2) {
    __shared__ float sW2[HID * OUTD];
    __shared__ float sb1[HID];
    int t = threadIdx.x;
    if (t < HID * OUTD) sW2[t] = W2[t];
    if (t < HID)        sb1[t] = b1[t];
    __syncthreads();

    int i = blockIdx.x * 256 + t;
    if (i >= N_NODES) return;

    const float4* hp = (const float4*)&g_H[i * HID];
    float h[16];
    *(float4*)&h[0]  = hp[0]; *(float4*)&h[4]  = hp[1];
    *(float4*)&h[8]  = hp[2]; *(float4*)&h[12] = hp[3];
#pragma unroll
    for (int j = 0; j < 16; j++) h[j] = fmaxf(h[j] + sb1[j], 0.f);

    float o[OUTP];
#pragma unroll
    for (int c = 0; c < OUTD; c++) {
        float s = 0.f;
#pragma unroll
        for (int j = 0; j < HID; j++) s = fmaf(h[j], sW2[j * OUTD + c], s);
        o[c] = s;
    }
    o[7] = 0.f;

    float4* d = (float4*)&g_HW2[i * OUTP];
    d[0] = *(float4*)&o[0];
    d[1] = *(float4*)&o[4];
}

// -------- SPMM2 + bias fused: warp per row, 2 lanes per edge, 16 edges/iter --------
__global__ void __launch_bounds__(256) spmm2_kernel(const float* __restrict__ b2,
                                                    float* __restrict__ out) {
    int warp = (blockIdx.x * 256 + threadIdx.x) >> 5;
    if (warp >= N_NODES) return;
    int lane = threadIdx.x & 31;
    int e    = lane >> 1;                 // edge sub-slot 0..15
    int dg   = lane & 1;                  // dim group (4 floats)

    int start = g_rowptr[warp];
    int end   = g_rowptr[warp + 1];

    float4 acc = make_float4(0.f, 0.f, 0.f, 0.f);
    int i = start + e;
    for (; i + 16 < end; i += 32) {
        ull e0 = g_edge[i];
        ull e1 = g_edge[i + 16];
        int   c0 = (int)(unsigned)e0;  float v0 = __uint_as_float((unsigned)(e0 >> 32));
        int   c1 = (int)(unsigned)e1;  float v1 = __uint_as_float((unsigned)(e1 >> 32));
        float4 x0 = *(const float4*)&g_HW2[c0 * OUTP + 4 * dg];
        float4 x1 = *(const float4*)&g_HW2[c1 * OUTP + 4 * dg];
        acc.x = fmaf(v0, x0.x, acc.x); acc.y = fmaf(v0, x0.y, acc.y);
        acc.z = fmaf(v0, x0.z, acc.z); acc.w = fmaf(v0, x0.w, acc.w);
        acc.x = fmaf(v1, x1.x, acc.x); acc.y = fmaf(v1, x1.y, acc.y);
        acc.z = fmaf(v1, x1.z, acc.z); acc.w = fmaf(v1, x1.w, acc.w);
    }
    if (i < end) {
        ull e0 = g_edge[i];
        int   c0 = (int)(unsigned)e0;  float v0 = __uint_as_float((unsigned)(e0 >> 32));
        float4 x0 = *(const float4*)&g_HW2[c0 * OUTP + 4 * dg];
        acc.x = fmaf(v0, x0.x, acc.x); acc.y = fmaf(v0, x0.y, acc.y);
        acc.z = fmaf(v0, x0.z, acc.z); acc.w = fmaf(v0, x0.w, acc.w);
    }
    // reduce across edge sub-slots (lane bits 1..4)
#pragma unroll
    for (int m = 2; m <= 16; m <<= 1) {
        acc.x += __shfl_xor_sync(0xffffffff, acc.x, m);
        acc.y += __shfl_xor_sync(0xffffffff, acc.y, m);
        acc.z += __shfl_xor_sync(0xffffffff, acc.z, m);
        acc.w += __shfl_xor_sync(0xffffffff, acc.w, m);
    }
    if (lane < 2) {
        int base = warp * OUTD + 4 * lane;
        float vals[4] = {acc.x, acc.y, acc.z, acc.w};
#pragma unroll
        for (int k = 0; k < 4; k++) {
            int col = 4 * lane + k;
            if (col < OUTD) out[base + k] = vals[k] + b2[col];
        }
    }
}

extern "C" void kernel_launch(void* const* d_in, const int* in_sizes, int n_in,
                              void* d_out, int out_size) {
    const float* feature = (const float*)d_in[0];
    const int*   erow    = (const int*)  d_in[1];
    const int*   ecol    = (const int*)  d_in[2];
    const float* evals   = (const float*)d_in[3];
    const float* W1      = (const float*)d_in[4];
    const float* b1      = (const float*)d_in[5];
    const float* W2      = (const float*)d_in[6];
    const float* b2      = (const float*)d_in[7];
    float* out = (float*)d_out;

    int quad_blocks  = (N_EDGES / 4 + 255) / 256;          // 6250
    int node_blocks  = (N_NODES + 255) / 256;              // 782
    int warp_blocks  = (N_NODES * 32 + 255) / 256;         // 25000
    const int ZB = 261, ZC = ZB * 256;                     // zero third = 66816

    // zero split in 3 so the fat gemm1+count kernel sits at launch index 3 (profiled)
    zero_kernel<<<ZB, 256>>>(0);                           // 0
    zero_kernel<<<ZB, 256>>>(ZC);                          // 1
    zero_kernel<<<ZB, 256>>>(2 * ZC);                      // 2
    gemm1_count_kernel<<<FAT_BLOCKS, 256>>>(feature, W1, erow);  // 3  <- profiled
    scan1_kernel<<<SCAN_BLOCKS, 256>>>();                  // 4
    scan2_kernel<<<1, 1024>>>();                           // 5
    scan3_kernel<<<SCAN_BLOCKS, 256>>>();                  // 6
    scatter_kernel<<<quad_blocks, 256>>>(erow, ecol, evals);
    spmm1_kernel<<<warp_blocks, 256>>>();
    gemm2_kernel<<<node_blocks, 256>>>(b1, W2);
    spmm2_kernel<<<warp_blocks, 256>>>(b2, out);
}